// round 14
// baseline (speedup 1.0000x reference)
#include <cuda_runtime.h>
#include <cstdint>

// Problem constants
#define NN 8
#define CC 128
#define HH 56
#define WW 56
#define COo 16
#define HWSZ (HH*WW)

// Conv tiling
#define S_SPLIT 16           // K-split over channels (16 groups of 8 channels)
#define KC 8                 // channels per tile
#define KCS 4                // channels per smem chunk (2 chunks per tile)
#define TH 8                 // output rows per tile
#define TROWS 16             // input rows incl. halo
#define TCSTRIDE 92          // 92 % 32 == 28 -> warp-spanning lanes hit disjoint banks
#define THREADS_A 256        // 8 warps: 7 compute warps (8 rows x 28 cols), all 8 stage
#define NTILES 896           // 7 ht x 8 n x 16 s
#define SPLIT_START 888      // last 8 tiles split into 2 half-pixel units each
#define NUNITS 904           // 888 full + 16 half units
#define OCC_A 3
#define GRID_A (148*OCC_A)   // 444 persistent blocks = exactly one resident wave
#define WCHUNK (KCS*35*COo)  // 2240 weight floats per chunk = 560 uint4
#define WT_ELEMS (CC*35*COo) // 71680
#define WT_PER_BLK 162       // ceil(71680 / 444)

// Split-K scratch: [S][N][CO][H*W]  (25.7 MB)
__device__ float g_ypart[S_SPLIT * NN * COo * HWSZ];
// Transposed conv weights: wT[c][t][o] (o contiguous).
__device__ __align__(16) float g_wT[WT_ELEMS];
// Fused epilogue weights: W = w5 @ w4, [o][j] (128 x 16).
__device__ float g_W[CC * COo];
// Dynamic unit counter + prep barrier. Both reset by the epilogue kernel
// (strictly stream-ordered between replays); static init covers call #1.
__device__ unsigned g_ctr = GRID_A;
__device__ unsigned g_prep_done = 0;

__device__ __forceinline__ unsigned long long pack2(float x) {
    unsigned long long r;
    unsigned int xi = __float_as_uint(x);
    asm("mov.b64 %0, {%1, %1};" : "=l"(r) : "r"(xi));
    return r;
}
__device__ __forceinline__ unsigned long long ffma2(unsigned long long a,
                                                    unsigned long long b,
                                                    unsigned long long c) {
    unsigned long long d;
    asm("fma.rn.f32x2 %0, %1, %2, %3;" : "=l"(d) : "l"(a), "l"(b), "l"(c));
    return d;
}
__device__ __forceinline__ void unpack2(unsigned long long v, float& lo, float& hi) {
    unsigned int l, h;
    asm("mov.b64 {%0, %1}, %2;" : "=r"(l), "=r"(h) : "l"(v));
    lo = __uint_as_float(l);
    hi = __uint_as_float(h);
}

__device__ __forceinline__ void cp_async16(uint32_t dst_smem, const void* src, unsigned src_size) {
    asm volatile("cp.async.cg.shared.global [%0], [%1], 16, %2;\n"
                 :: "r"(dst_smem), "l"(src), "r"(src_size));
}
__device__ __forceinline__ void cp_commit() {
    asm volatile("cp.async.commit_group;\n");
}
template<int N>
__device__ __forceinline__ void cp_wait() {
    asm volatile("cp.async.wait_group %0;\n" :: "n"(N));
}

// ---------------------------------------------------------------------------
// Kernel A: prep prologue (w3 transpose + W=w5@w4 + spin barrier), then
// dilated 5x7 conv (C->CO), split-K over 16 channel groups, persistent
// blocks pulling units dynamically. 16B cp.async double-buffered staging.
// 7 compute warps: 2 pixels x 16 CO as 16 f32x2 regs (half-pixel tail units
// compute/store only acc0).
// ---------------------------------------------------------------------------
__global__ __launch_bounds__(THREADS_A, OCC_A)
void conv_kernel(const float* __restrict__ x, const float* __restrict__ w3,
                 const float* __restrict__ w4, const float* __restrict__ w5) {
    __shared__ __align__(16) float xs[2][KCS][TROWS][TCSTRIDE];
    __shared__ __align__(16) float ws[2][KCS][5][7][COo];   // [buf][ci][kh][kw][o]
    __shared__ unsigned s_next;

    const int tid = threadIdx.x;

    // ---- Prep phase: distributed transpose + W, then grid-wide spin ----
    {
        int base = (int)blockIdx.x * WT_PER_BLK;
#pragma unroll 1
        for (int i = tid; i < WT_PER_BLK; i += THREADS_A) {
            int idx = base + i;
            if (idx < WT_ELEMS) {
                int o  = idx & 15;
                int ct = idx >> 4;         // c*35 + t
                int c  = ct / 35;
                int t  = ct % 35;
                g_wT[idx] = w3[((size_t)o * CC + c) * 35 + t];
            }
        }
        if (blockIdx.x < 8) {
            int e = (int)blockIdx.x * THREADS_A + tid;   // 0..2047
            int o = e >> 4, j = e & 15;
            float v = 0.0f;
#pragma unroll
            for (int c = 0; c < COo; c++) v += w5[o * COo + c] * w4[c * COo + j];
            g_W[e] = v;
        }
        __threadfence();
        __syncthreads();                 // block's slice done
        if (tid == 0) {
            atomicAdd(&g_prep_done, 1u);
            unsigned v;
            do {
                asm volatile("ld.global.acquire.gpu.u32 %0, [%1];"
                             : "=r"(v) : "l"(&g_prep_done));
            } while (v < GRID_A);
        }
        __syncthreads();                 // all blocks' prep visible
    }

    const int r  = (tid < 224) ? tid / 28 : 0;   // compute row (warps 0..6)
    const int wg = (tid < 224) ? tid % 28 : 0;   // first pixel col

    const uint32_t xs_base = (uint32_t)__cvta_generic_to_shared(&xs[0][0][0][0]);
    const uint32_t ws_base = (uint32_t)__cvta_generic_to_shared(&ws[0][0][0][0]);

    // Stage one KCS-channel chunk of x + weights into buffer `buf` (async).
    auto stage_chunk = [&](int buf, int n, int h0, int cbase_cc) {
#pragma unroll
        for (int i = 0; i < 5; i++) {
            int idx = tid + i * THREADS_A;       // 0..1279
            int row = idx / 20;                  // 0..63
            int v   = idx % 20;                  // 16B vector within row
            int ci  = row >> 4;
            int tr  = row & 15;
            int h_in = h0 - 4 + tr;
            int w0   = v * 4 - 12;               // first w_in of this vector
            bool ok = ((unsigned)h_in < HH) & (w0 >= 0) & (w0 + 3 < WW);
            const float* src = ok
                ? x + (((size_t)n * CC + (cbase_cc + ci)) * HH + h_in) * WW + w0
                : x;                             // valid addr; size=0 -> zfill
            uint32_t dst = xs_base +
                (((buf * KCS + ci) * TROWS + tr) * TCSTRIDE + v * 4) * 4;
            cp_async16(dst, src, ok ? 16u : 0u);
        }
        const float* wsrc = g_wT + (size_t)cbase_cc * 35 * COo;
        uint32_t wdst = ws_base + (buf * WCHUNK) * 4;
#pragma unroll
        for (int i = 0; i < 3; i++) {
            int k = tid + i * THREADS_A;
            if (k < WCHUNK / 4)
                cp_async16(wdst + k * 16, wsrc + k * 4, 16u);
        }
    };

    unsigned long long acc0[8], acc1[8];
    int wgp = wg;            // acc0 pixel column (wg, or wg+28 for half=1 units)
    bool fullmode = true;

    auto compute_chunk = [&](int buf) {
        if (tid >= 224) return;
#pragma unroll 1
        for (int ci = 0; ci < KCS; ci++) {
#pragma unroll
            for (int kh = 0; kh < 5; kh++) {
                const float* xrow = &xs[buf][ci][r + 2 * kh][0];
#pragma unroll
                for (int kw = 0; kw < 7; kw++) {
                    // staged col = w_in + 12; needed w_in = px - 9 + 3kw
                    float xa = xrow[wgp + 3 * kw + 3];
                    unsigned long long xa2 = pack2(xa);
                    const ulonglong2* wp = (const ulonglong2*)&ws[buf][ci][kh][kw][0];
                    ulonglong2 wv0 = wp[0], wv1 = wp[1], wv2 = wp[2], wv3 = wp[3];
                    acc0[0] = ffma2(xa2, wv0.x, acc0[0]);
                    acc0[1] = ffma2(xa2, wv0.y, acc0[1]);
                    acc0[2] = ffma2(xa2, wv1.x, acc0[2]);
                    acc0[3] = ffma2(xa2, wv1.y, acc0[3]);
                    acc0[4] = ffma2(xa2, wv2.x, acc0[4]);
                    acc0[5] = ffma2(xa2, wv2.y, acc0[5]);
                    acc0[6] = ffma2(xa2, wv3.x, acc0[6]);
                    acc0[7] = ffma2(xa2, wv3.y, acc0[7]);
                    if (fullmode) {
                        float xb = xrow[wg + 28 + 3 * kw + 3];
                        unsigned long long xb2 = pack2(xb);
                        acc1[0] = ffma2(xb2, wv0.x, acc1[0]);
                        acc1[1] = ffma2(xb2, wv0.y, acc1[1]);
                        acc1[2] = ffma2(xb2, wv1.x, acc1[2]);
                        acc1[3] = ffma2(xb2, wv1.y, acc1[3]);
                        acc1[4] = ffma2(xb2, wv2.x, acc1[4]);
                        acc1[5] = ffma2(xb2, wv2.y, acc1[5]);
                        acc1[6] = ffma2(xb2, wv3.x, acc1[6]);
                        acc1[7] = ffma2(xb2, wv3.y, acc1[7]);
                    }
                }
            }
        }
    };

    // Unit decode: units 0..887 = full tiles; 888..903 = half-pixel units.
    auto decode = [&](unsigned u, int& n, int& h0, int& cbase, int& s, int& half) {
        int tile;
        if (u < SPLIT_START) { tile = (int)u; half = -1; }
        else { int k = (int)u - SPLIT_START; tile = SPLIT_START + (k >> 1); half = k & 1; }
        s = tile / 56;
        int rem = tile % 56;
        n = rem / 7;
        h0 = (rem % 7) * TH;
        cbase = s * KC;
    };

    unsigned unit = blockIdx.x;          // < 444 < 888 -> always a full tile
    int n, h0, cbase, s, half;
    decode(unit, n, h0, cbase, s, half);
    wgp = wg; fullmode = true;

    stage_chunk(0, n, h0, cbase);
    cp_commit();                               // pending: {cur.c0}

    while (true) {
        stage_chunk(1, n, h0, cbase + KCS);
        cp_commit();                           // pending: {cur.c0, cur.c1}
        if (tid == 0) s_next = atomicAdd(&g_ctr, 1u);

#pragma unroll
        for (int j = 0; j < 8; j++) { acc0[j] = 0ull; acc1[j] = 0ull; }

        cp_wait<1>();                          // cur.c0 landed
        __syncthreads();
        compute_chunk(0);
        __syncthreads();                       // buf0 free; s_next visible

        unsigned nu = s_next;
        bool have_next = nu < NUNITS;
        int nn = 0, nh0 = 0, ncb = 0, ns = 0, nhalf = -1;
        if (have_next) {
            decode(nu, nn, nh0, ncb, ns, nhalf);
            stage_chunk(0, nn, nh0, ncb);      // prefetch next unit's chunk0
            cp_commit();                       // pending: {cur.c1, next.c0}
            cp_wait<1>();                      // cur.c1 landed
        } else {
            cp_wait<0>();
        }
        __syncthreads();
        compute_chunk(1);

        // Store partials: g_ypart[s][n][o][h*56 + w]
        if (tid < 224) {
            const int h = h0 + r;
            float* yp = &g_ypart[(((size_t)s * NN + n) * COo) * HWSZ + h * WW];
            if (fullmode) {
#pragma unroll
                for (int j = 0; j < 8; j++) {
                    float lo, hi;
                    unpack2(acc0[j], lo, hi);
                    yp[(2*j)   * HWSZ + wg] = lo;
                    yp[(2*j+1) * HWSZ + wg] = hi;
                    unpack2(acc1[j], lo, hi);
                    yp[(2*j)   * HWSZ + wg + 28] = lo;
                    yp[(2*j+1) * HWSZ + wg + 28] = hi;
                }
            } else {
#pragma unroll
                for (int j = 0; j < 8; j++) {
                    float lo, hi;
                    unpack2(acc0[j], lo, hi);
                    yp[(2*j)   * HWSZ + wgp] = lo;
                    yp[(2*j+1) * HWSZ + wgp] = hi;
                }
            }
        }

        if (!have_next) break;
        n = nn; h0 = nh0; cbase = ncb; s = ns; half = nhalf;
        fullmode = (half < 0);
        wgp = wg + ((half == 1) ? 28 : 0);
        __syncthreads();   // everyone done reading buf1 before it's re-staged
    }
}

// ---------------------------------------------------------------------------
// Kernel B: reduce 16 split-K partials, apply fused W = w5@w4 (128x16).
// 896 blocks (one per (half-row, n)) x 224 threads: px = tid%28 (half-row
// pixel), q = tid/28 reduces 2 slices and emits 16 output channels.
// Also resets the conv counters for the next graph replay.
// ---------------------------------------------------------------------------
__global__ __launch_bounds__(224)
void epilogue_kernel(float* __restrict__ out) {
    __shared__ float Wsh[CC * COo];
    __shared__ float ysh[COo][8][29];   // [c][q][px]
    const int tid = threadIdx.x;

    // Reset conv's counters for the next replay (conv already finished).
    if (blockIdx.x == 0 && blockIdx.y == 0 && tid == 0) {
        g_ctr = GRID_A;
        g_prep_done = 0;
    }

    for (int i = tid; i < CC * COo; i += 224) Wsh[i] = g_W[i];

    const int n   = blockIdx.y;
    const int h   = blockIdx.x >> 1;
    const int pxb = (blockIdx.x & 1) * 28;
    const int px  = tid % 28;
    const int q   = tid / 28;          // 0..7
    const int p   = h * WW + pxb + px;
    __syncthreads();

    // partial reduction: each thread sums 2 of the 16 s-slices for all 16 c
#pragma unroll
    for (int c = 0; c < COo; c++) {
        float v = g_ypart[((((size_t)(q*2)   * NN + n) * COo + c)) * HWSZ + p]
                + g_ypart[((((size_t)(q*2+1) * NN + n) * COo + c)) * HWSZ + p];
        ysh[c][q][px] = v;
    }
    __syncthreads();

    float y[COo];
#pragma unroll
    for (int c = 0; c < COo; c++) {
        float v = 0.0f;
#pragma unroll
        for (int qq = 0; qq < 8; qq++) v += ysh[c][qq][px];
        y[c] = v;
    }

    float* outp = out + ((size_t)n * CC) * HWSZ + p;
#pragma unroll 4
    for (int oo = 0; oo < 16; oo++) {
        int o = q * 16 + oo;
        float v = 0.0f;
#pragma unroll
        for (int j = 0; j < COo; j++) v += Wsh[o * COo + j] * y[j];
        outp[(size_t)o * HWSZ] = v;
    }
}

// ---------------------------------------------------------------------------
extern "C" void kernel_launch(void* const* d_in, const int* in_sizes, int n_in,
                              void* d_out, int out_size) {
    const float* x  = (const float*)d_in[0];
    const float* w3 = (const float*)d_in[1];
    const float* w4 = (const float*)d_in[2];
    const float* w5 = (const float*)d_in[3];
    float* out = (float*)d_out;

    conv_kernel<<<GRID_A, THREADS_A>>>(x, w3, w4, w5);  // prep + conv fused
    dim3 gridB(112, NN);                                // 896 blocks
    epilogue_kernel<<<gridB, 224>>>(out);
}

// round 15
// speedup vs baseline: 1.0334x; 1.0334x over previous
#include <cuda_runtime.h>
#include <cstdint>

// Problem constants
#define NN 8
#define CC 128
#define HH 56
#define WW 56
#define COo 16
#define HWSZ (HH*WW)

// Conv tiling
#define S_SPLIT 16           // K-split over channels (16 groups of 8 channels)
#define KC 8                 // channels per tile
#define KCS 4                // channels per smem chunk (2 chunks per tile)
#define TH 8                 // output rows per tile
#define TROWS 16             // input rows incl. halo
#define TCSTRIDE 92          // 92 % 32 == 28 -> warp-spanning lanes hit disjoint banks
#define THREADS_A 256        // 8 warps: 7 compute warps (8 rows x 28 cols), all 8 stage
#define NFULL 888            // full tiles 0..887 (tiles 888..895 are split)
#define NUNITS 904           // 888 full + 16 channel-half units
#define SPLIT_START 888
#define OCC_A 3
#define GRID_A (148*OCC_A)   // 444 persistent blocks = exactly one resident wave
#define WCHUNK (KCS*35*COo)  // 2240 weight floats per chunk = 560 uint4
#define WT_ELEMS (CC*35*COo) // 71680
// Tail zero region: tiles 888-895 = s=15, (n=6 rows 48-55) + (n=7 rows 0-55)
#define ZERO_A_ELEMS (COo*8*WW)    // 7168
#define ZERO_B_ELEMS (COo*HWSZ)    // 50176
#define ZERO_TOT_V4 ((ZERO_A_ELEMS+ZERO_B_ELEMS)/4)  // 14336 float4

// Split-K scratch: [S][N][CO][H*W]  (25.7 MB)
__device__ __align__(16) float g_ypart[S_SPLIT * NN * COo * HWSZ];
// Transposed conv weights: wT[c][t][o] (o contiguous).
__device__ __align__(16) float g_wT[WT_ELEMS];
// Fused epilogue weights: W = w5 @ w4, [o][j] (128 x 16).
__device__ float g_W[CC * COo];
// Dynamic unit counter (reset by prep each replay; static init covers call #1).
__device__ unsigned g_ctr = GRID_A;

__device__ __forceinline__ unsigned long long pack2(float x) {
    unsigned long long r;
    unsigned int xi = __float_as_uint(x);
    asm("mov.b64 %0, {%1, %1};" : "=l"(r) : "r"(xi));
    return r;
}
__device__ __forceinline__ unsigned long long ffma2(unsigned long long a,
                                                    unsigned long long b,
                                                    unsigned long long c) {
    unsigned long long d;
    asm("fma.rn.f32x2 %0, %1, %2, %3;" : "=l"(d) : "l"(a), "l"(b), "l"(c));
    return d;
}
__device__ __forceinline__ void unpack2(unsigned long long v, float& lo, float& hi) {
    unsigned int l, h;
    asm("mov.b64 {%0, %1}, %2;" : "=r"(l), "=r"(h) : "l"(v));
    lo = __uint_as_float(l);
    hi = __uint_as_float(h);
}

__device__ __forceinline__ void cp_async16(uint32_t dst_smem, const void* src, unsigned src_size) {
    asm volatile("cp.async.cg.shared.global [%0], [%1], 16, %2;\n"
                 :: "r"(dst_smem), "l"(src), "r"(src_size));
}
__device__ __forceinline__ void cp_commit() {
    asm volatile("cp.async.commit_group;\n");
}
template<int N>
__device__ __forceinline__ void cp_wait() {
    asm volatile("cp.async.wait_group %0;\n" :: "n"(N));
}

// ---------------------------------------------------------------------------
// Prep kernel: (a) transpose w3 -> wT[c][t][o]; (b) W = w5 @ w4; (c) reset
// tile counter; (d) zero the tail atomic-accumulation region.
// Grid 172 x 512: b 0..139 wT, b 140..143 W, b 144..171 zero tail region.
// ---------------------------------------------------------------------------
__global__ __launch_bounds__(512)
void prep_kernel(const float* __restrict__ w3, const float* __restrict__ w4,
                 const float* __restrict__ w5) {
    if (blockIdx.x == 0 && threadIdx.x == 0) g_ctr = GRID_A;
    int b = blockIdx.x;
    if (b < 140) {
        int idx = b * 512 + threadIdx.x;      // 0..71679
        int o  = idx & 15;
        int ct = idx >> 4;                    // c*35 + t
        int c  = ct / 35;
        int t  = ct % 35;
        g_wT[idx] = w3[((size_t)o * CC + c) * 35 + t];
    } else if (b < 144) {
        int e = (b - 140) * 512 + threadIdx.x; // 0..2047
        int o = e >> 4, j = e & 15;
        float v = 0.0f;
#pragma unroll
        for (int c = 0; c < COo; c++) v += w5[o * COo + c] * w4[c * COo + j];
        g_W[e] = v;
    } else {
        // zero tail region (float4): A = (s15,n6) rows 48-55; B = (s15,n7) all
        int t = (b - 144) * 512 + threadIdx.x;   // 0..14335
        float4 z = make_float4(0.f, 0.f, 0.f, 0.f);
        if (t < ZERO_A_ELEMS / 4) {
            int e = t * 4;                       // within A: [c][448]
            int c = e / (8 * WW);
            int q = e % (8 * WW);
            size_t off = (((size_t)15 * NN + 6) * COo + c) * HWSZ + 48 * WW + q;
            *(float4*)(g_ypart + off) = z;
        } else {
            int e = (t - ZERO_A_ELEMS / 4) * 4;  // within B: [c][3136]
            int c = e / HWSZ;
            int q = e % HWSZ;
            size_t off = (((size_t)15 * NN + 7) * COo + c) * HWSZ + q;
            *(float4*)(g_ypart + off) = z;
        }
    }
}

// ---------------------------------------------------------------------------
// Kernel A: dilated 5x7 conv (C->CO), split-K over 16 channel groups.
// Persistent blocks pull units dynamically; 16B cp.async double-buffered
// staging. Units 0..887 = full tiles (2 chunks, plain store). Units 888..903
// = channel-half units of tiles 888..895 (1 chunk, atomicAdd into the
// pre-zeroed region) -- processed in a simple phase-2 after full tiles.
// 7 compute warps: 2 pixels (w, w+28) x 16 CO as 16 f32x2 regs.
// ---------------------------------------------------------------------------
__global__ __launch_bounds__(THREADS_A, OCC_A)
void conv_partial_kernel(const float* __restrict__ x) {
    __shared__ __align__(16) float xs[2][KCS][TROWS][TCSTRIDE];
    __shared__ __align__(16) float ws[2][KCS][5][7][COo];   // [buf][ci][kh][kw][o]
    __shared__ unsigned s_next;

    const int tid  = threadIdx.x;
    const int r  = (tid < 224) ? tid / 28 : 0;   // compute row (warps 0..6)
    const int wg = (tid < 224) ? tid % 28 : 0;   // first pixel col (second = +28)

    const uint32_t xs_base = (uint32_t)__cvta_generic_to_shared(&xs[0][0][0][0]);
    const uint32_t ws_base = (uint32_t)__cvta_generic_to_shared(&ws[0][0][0][0]);

    // Stage one KCS-channel chunk of x + weights into buffer `buf` (async).
    auto stage_chunk = [&](int buf, int n, int h0, int cbase_cc) {
#pragma unroll
        for (int i = 0; i < 5; i++) {
            int idx = tid + i * THREADS_A;       // 0..1279
            int row = idx / 20;                  // 0..63
            int v   = idx % 20;                  // 16B vector within row
            int ci  = row >> 4;
            int tr  = row & 15;
            int h_in = h0 - 4 + tr;
            int w0   = v * 4 - 12;               // first w_in of this vector
            bool ok = ((unsigned)h_in < HH) & (w0 >= 0) & (w0 + 3 < WW);
            const float* src = ok
                ? x + (((size_t)n * CC + (cbase_cc + ci)) * HH + h_in) * WW + w0
                : x;                             // valid addr; size=0 -> zfill
            uint32_t dst = xs_base +
                (((buf * KCS + ci) * TROWS + tr) * TCSTRIDE + v * 4) * 4;
            cp_async16(dst, src, ok ? 16u : 0u);
        }
        const float* wsrc = g_wT + (size_t)cbase_cc * 35 * COo;
        uint32_t wdst = ws_base + (buf * WCHUNK) * 4;
#pragma unroll
        for (int i = 0; i < 3; i++) {
            int k = tid + i * THREADS_A;
            if (k < WCHUNK / 4)
                cp_async16(wdst + k * 16, wsrc + k * 4, 16u);
        }
    };

    unsigned long long acc0[8], acc1[8];
    auto compute_chunk = [&](int buf) {
        if (tid >= 224) return;
#pragma unroll
        for (int ci = 0; ci < KCS; ci++) {
#pragma unroll
            for (int kh = 0; kh < 5; kh++) {
                const float* xrow = &xs[buf][ci][r + 2 * kh][0];
#pragma unroll
                for (int kw = 0; kw < 7; kw++) {
                    // staged col = w_in + 12; needed w_in = px - 9 + 3kw
                    float xa = xrow[wg + 3 * kw + 3];
                    float xb = xrow[wg + 28 + 3 * kw + 3];
                    unsigned long long xa2 = pack2(xa);
                    unsigned long long xb2 = pack2(xb);
                    const ulonglong2* wp = (const ulonglong2*)&ws[buf][ci][kh][kw][0];
#pragma unroll
                    for (int q = 0; q < 4; q++) {
                        ulonglong2 wv = wp[q];
                        acc0[2*q]   = ffma2(xa2, wv.x, acc0[2*q]);
                        acc0[2*q+1] = ffma2(xa2, wv.y, acc0[2*q+1]);
                        acc1[2*q]   = ffma2(xb2, wv.x, acc1[2*q]);
                        acc1[2*q+1] = ffma2(xb2, wv.y, acc1[2*q+1]);
                    }
                }
            }
        }
    };

    // ---- Phase 1: full tiles (units < 888), double-buffered pipeline ----
    unsigned tile = blockIdx.x;              // 0..443, always a full tile
    int n  = (tile / 7) & (NN - 1);
    int s  = tile / 56;
    int h0 = (tile % 7) * TH;
    int cbase = s * KC;

    stage_chunk(0, n, h0, cbase);
    cp_commit();                               // pending: {cur.c0}

    unsigned nu = NUNITS;                      // carries exit counter value
    while (true) {
        stage_chunk(1, n, h0, cbase + KCS);
        cp_commit();                           // pending: {cur.c0, cur.c1}
        if (tid == 0) s_next = atomicAdd(&g_ctr, 1u);

#pragma unroll
        for (int j = 0; j < 8; j++) { acc0[j] = 0ull; acc1[j] = 0ull; }

        cp_wait<1>();                          // cur.c0 landed
        __syncthreads();
        compute_chunk(0);
        __syncthreads();                       // buf0 free; s_next visible

        nu = s_next;
        bool have_next = nu < NFULL;
        int nn = 0, nh0 = 0, ncb = 0;
        if (have_next) {
            nn = (nu / 7) & (NN - 1);
            nh0 = (nu % 7) * TH;
            ncb = (nu / 56) * KC;
            stage_chunk(0, nn, nh0, ncb);      // prefetch next tile's chunk0
            cp_commit();                       // pending: {cur.c1, next.c0}
            cp_wait<1>();                      // cur.c1 landed
        } else {
            cp_wait<0>();
        }
        __syncthreads();
        compute_chunk(1);

        // Store partials: g_ypart[s][n][o][h*56 + w]
        if (tid < 224) {
            const int h = h0 + r;
            float* yp = &g_ypart[(((size_t)s * NN + n) * COo) * HWSZ + h * WW];
#pragma unroll
            for (int j = 0; j < 8; j++) {
                float lo, hi;
                unpack2(acc0[j], lo, hi);
                yp[(2*j)   * HWSZ + wg] = lo;
                yp[(2*j+1) * HWSZ + wg] = hi;
                unpack2(acc1[j], lo, hi);
                yp[(2*j)   * HWSZ + wg + 28] = lo;
                yp[(2*j+1) * HWSZ + wg + 28] = hi;
            }
        }

        if (!have_next) break;
        n = nn; h0 = nh0; cbase = ncb; s = nu / 56;
        __syncthreads();   // everyone done reading buf1 before it's re-staged
    }

    // ---- Phase 2: channel-half tail units (888..903), simple path ----
    // Each unit = one 4-channel chunk of a tail tile; accumulate via RED.ADD
    // onto the region prep pre-zeroed (2 commutative adds -> deterministic).
    while (nu < NUNITS) {
        int k    = (int)nu - SPLIT_START;
        int tl   = SPLIT_START + (k >> 1);     // tile 888..895 (s = 15)
        int hc   = k & 1;                      // which 4-channel half
        int n_   = (tl / 7) & (NN - 1);
        int h0_  = (tl % 7) * TH;
        int cb   = 15 * KC + hc * KCS;

        __syncthreads();                       // prior readers of buf0 done
        stage_chunk(0, n_, h0_, cb);
        cp_commit();
        cp_wait<0>();
        __syncthreads();

#pragma unroll
        for (int j = 0; j < 8; j++) { acc0[j] = 0ull; acc1[j] = 0ull; }
        compute_chunk(0);

        if (tid < 224) {
            const int h = h0_ + r;
            float* yp = &g_ypart[(((size_t)15 * NN + n_) * COo) * HWSZ + h * WW];
#pragma unroll
            for (int j = 0; j < 8; j++) {
                float lo, hi;
                unpack2(acc0[j], lo, hi);
                atomicAdd(&yp[(2*j)   * HWSZ + wg], lo);
                atomicAdd(&yp[(2*j+1) * HWSZ + wg], hi);
                unpack2(acc1[j], lo, hi);
                atomicAdd(&yp[(2*j)   * HWSZ + wg + 28], lo);
                atomicAdd(&yp[(2*j+1) * HWSZ + wg + 28], hi);
            }
        }

        if (tid == 0) s_next = atomicAdd(&g_ctr, 1u);
        __syncthreads();
        nu = s_next;
    }
}

// ---------------------------------------------------------------------------
// Kernel B: reduce 16 split-K partials, apply fused W = w5@w4 (128x16).
// 448 blocks (one per (row, n)); 4 threads per pixel (best measured shape).
// ---------------------------------------------------------------------------
__global__ __launch_bounds__(224)
void epilogue_kernel(float* __restrict__ out) {
    __shared__ float Wsh[CC * COo];
    __shared__ float ysh[COo][4][57];   // [c][q][px]
    const int tid = threadIdx.x;
    for (int i = tid; i < CC * COo; i += 224) Wsh[i] = g_W[i];

    const int n  = blockIdx.y;
    const int h  = blockIdx.x;
    const int px = tid % 56;
    const int q  = tid / 56;          // 0..3
    const int p  = h * WW + px;
    __syncthreads();

    // partial reduction: each thread sums 4 of the 16 s-slices for all 16 c
#pragma unroll
    for (int c = 0; c < COo; c++) {
        float v = 0.0f;
#pragma unroll
        for (int ss = 0; ss < 4; ss++) {
            int s = q * 4 + ss;
            v += g_ypart[(((size_t)s * NN + n) * COo + c) * HWSZ + p];
        }
        ysh[c][q][px] = v;
    }
    __syncthreads();

    float y[COo];
#pragma unroll
    for (int c = 0; c < COo; c++)
        y[c] = ysh[c][0][px] + ysh[c][1][px] + ysh[c][2][px] + ysh[c][3][px];

    float* outp = out + ((size_t)n * CC) * HWSZ + p;
#pragma unroll 4
    for (int oo = 0; oo < 32; oo++) {
        int o = q * 32 + oo;
        float v = 0.0f;
#pragma unroll
        for (int j = 0; j < COo; j++) v += Wsh[o * COo + j] * y[j];
        outp[(size_t)o * HWSZ] = v;
    }
}

// ---------------------------------------------------------------------------
extern "C" void kernel_launch(void* const* d_in, const int* in_sizes, int n_in,
                              void* d_out, int out_size) {
    const float* x  = (const float*)d_in[0];
    const float* w3 = (const float*)d_in[1];
    const float* w4 = (const float*)d_in[2];
    const float* w5 = (const float*)d_in[3];
    float* out = (float*)d_out;

    prep_kernel<<<172, 512>>>(w3, w4, w5);
    conv_partial_kernel<<<GRID_A, THREADS_A>>>(x);      // 444 persistent blocks
    dim3 gridB(HH, NN);                                 // 448 blocks
    epilogue_kernel<<<gridB, 224>>>(out);
}

// round 16
// speedup vs baseline: 1.0580x; 1.0238x over previous
#include <cuda_runtime.h>
#include <cstdint>

// Problem constants
#define NN 8
#define CC 128
#define HH 56
#define WW 56
#define COo 16
#define HWSZ (HH*WW)

// Conv tiling
#define S_SPLIT 16           // K-split over channels (16 groups of 8 channels)
#define KC 8                 // channels per tile
#define KCS 4                // channels per smem chunk (2 chunks per tile)
#define TH 8                 // output rows per tile
#define TROWS 16             // input rows incl. halo
#define TCSTRIDE 92          // 92 % 32 == 28 -> warp-spanning lanes hit disjoint banks
#define THREADS_A 256        // 8 warps: 7 compute warps (8 rows x 28 cols), all 8 stage
#define NTILES 896           // 7 ht x 8 n x 16 s
#define OCC_A 3
#define GRID_A (148*OCC_A)   // 444 persistent blocks = exactly one resident wave
#define WCHUNK (KCS*35*COo)  // 2240 weight floats per chunk = 560 uint4
#define WT_ELEMS (CC*35*COo) // 71680

// Split-K scratch, GEMM-friendly layout: [s][n][p][c], c contiguous (25.7 MB)
__device__ __align__(16) float g_ypart[S_SPLIT * NN * HWSZ * COo];
// Transposed conv weights: wT[c][t][o] (o contiguous).
__device__ __align__(16) float g_wT[WT_ELEMS];
// Fused epilogue weights: W = w5 @ w4, [o][j] (128 x 16).
__device__ float g_W[CC * COo];
// Dynamic tile counter (reset by prep each replay; static init covers call #1).
__device__ unsigned g_ctr = GRID_A;

__device__ __forceinline__ unsigned long long pack2(float x) {
    unsigned long long r;
    unsigned int xi = __float_as_uint(x);
    asm("mov.b64 %0, {%1, %1};" : "=l"(r) : "r"(xi));
    return r;
}
__device__ __forceinline__ unsigned long long ffma2(unsigned long long a,
                                                    unsigned long long b,
                                                    unsigned long long c) {
    unsigned long long d;
    asm("fma.rn.f32x2 %0, %1, %2, %3;" : "=l"(d) : "l"(a), "l"(b), "l"(c));
    return d;
}

__device__ __forceinline__ void cp_async16(uint32_t dst_smem, const void* src, unsigned src_size) {
    asm volatile("cp.async.cg.shared.global [%0], [%1], 16, %2;\n"
                 :: "r"(dst_smem), "l"(src), "r"(src_size));
}
__device__ __forceinline__ void cp_commit() {
    asm volatile("cp.async.commit_group;\n");
}
template<int N>
__device__ __forceinline__ void cp_wait() {
    asm volatile("cp.async.wait_group %0;\n" :: "n"(N));
}

// ---------------------------------------------------------------------------
// Prep kernel: (a) transpose w3 -> wT[c][t][o]; (b) W = w5 @ w4; (c) reset
// tile counter. Grid 144 x 512: b 0..139 wT, b 140..143 W.
// ---------------------------------------------------------------------------
__global__ __launch_bounds__(512)
void prep_kernel(const float* __restrict__ w3, const float* __restrict__ w4,
                 const float* __restrict__ w5) {
    if (blockIdx.x == 0 && threadIdx.x == 0) g_ctr = GRID_A;
    int b = blockIdx.x;
    if (b < 140) {
        int idx = b * 512 + threadIdx.x;      // 0..71679
        int o  = idx & 15;
        int ct = idx >> 4;                    // c*35 + t
        int c  = ct / 35;
        int t  = ct % 35;
        g_wT[idx] = w3[((size_t)o * CC + c) * 35 + t];
    } else {
        int e = (b - 140) * 512 + threadIdx.x; // 0..2047
        int o = e >> 4, j = e & 15;
        float v = 0.0f;
#pragma unroll
        for (int c = 0; c < COo; c++) v += w5[o * COo + c] * w4[c * COo + j];
        g_W[e] = v;
    }
}

// ---------------------------------------------------------------------------
// Kernel A: dilated 5x7 conv (C->CO), split-K over 16 channel groups.
// Persistent blocks pull tiles dynamically; 16B cp.async double-buffered
// staging. 7 compute warps: 2 pixels (w, w+28) x 16 CO as 16 f32x2 regs.
// Stores partials as [s][n][p][c] (c contiguous) via 8 x STG.128 per thread.
// ---------------------------------------------------------------------------
__global__ __launch_bounds__(THREADS_A, OCC_A)
void conv_partial_kernel(const float* __restrict__ x) {
    __shared__ __align__(16) float xs[2][KCS][TROWS][TCSTRIDE];
    __shared__ __align__(16) float ws[2][KCS][5][7][COo];   // [buf][ci][kh][kw][o]
    __shared__ unsigned s_next;

    const int tid  = threadIdx.x;
    const int r  = (tid < 224) ? tid / 28 : 0;   // compute row (warps 0..6)
    const int wg = (tid < 224) ? tid % 28 : 0;   // first pixel col (second = +28)

    const uint32_t xs_base = (uint32_t)__cvta_generic_to_shared(&xs[0][0][0][0]);
    const uint32_t ws_base = (uint32_t)__cvta_generic_to_shared(&ws[0][0][0][0]);

    // Stage one KCS-channel chunk of x + weights into buffer `buf` (async).
    auto stage_chunk = [&](int buf, int n, int h0, int cbase_cc) {
#pragma unroll
        for (int i = 0; i < 5; i++) {
            int idx = tid + i * THREADS_A;       // 0..1279
            int row = idx / 20;                  // 0..63
            int v   = idx % 20;                  // 16B vector within row
            int ci  = row >> 4;
            int tr  = row & 15;
            int h_in = h0 - 4 + tr;
            int w0   = v * 4 - 12;               // first w_in of this vector
            bool ok = ((unsigned)h_in < HH) & (w0 >= 0) & (w0 + 3 < WW);
            const float* src = ok
                ? x + (((size_t)n * CC + (cbase_cc + ci)) * HH + h_in) * WW + w0
                : x;                             // valid addr; size=0 -> zfill
            uint32_t dst = xs_base +
                (((buf * KCS + ci) * TROWS + tr) * TCSTRIDE + v * 4) * 4;
            cp_async16(dst, src, ok ? 16u : 0u);
        }
        const float* wsrc = g_wT + (size_t)cbase_cc * 35 * COo;
        uint32_t wdst = ws_base + (buf * WCHUNK) * 4;
#pragma unroll
        for (int i = 0; i < 3; i++) {
            int k = tid + i * THREADS_A;
            if (k < WCHUNK / 4)
                cp_async16(wdst + k * 16, wsrc + k * 4, 16u);
        }
    };

    unsigned long long acc0[8], acc1[8];
    auto compute_chunk = [&](int buf) {
        if (tid >= 224) return;
#pragma unroll
        for (int ci = 0; ci < KCS; ci++) {
#pragma unroll
            for (int kh = 0; kh < 5; kh++) {
                const float* xrow = &xs[buf][ci][r + 2 * kh][0];
#pragma unroll
                for (int kw = 0; kw < 7; kw++) {
                    // staged col = w_in + 12; needed w_in = px - 9 + 3kw
                    float xa = xrow[wg + 3 * kw + 3];
                    float xb = xrow[wg + 28 + 3 * kw + 3];
                    unsigned long long xa2 = pack2(xa);
                    unsigned long long xb2 = pack2(xb);
                    const ulonglong2* wp = (const ulonglong2*)&ws[buf][ci][kh][kw][0];
#pragma unroll
                    for (int q = 0; q < 4; q++) {
                        ulonglong2 wv = wp[q];
                        acc0[2*q]   = ffma2(xa2, wv.x, acc0[2*q]);
                        acc0[2*q+1] = ffma2(xa2, wv.y, acc0[2*q+1]);
                        acc1[2*q]   = ffma2(xb2, wv.x, acc1[2*q]);
                        acc1[2*q+1] = ffma2(xb2, wv.y, acc1[2*q+1]);
                    }
                }
            }
        }
    };

    unsigned tile = blockIdx.x;
    int n  = (tile / 7) & (NN - 1);
    int s  = tile / 56;
    int h0 = (tile % 7) * TH;
    int cbase = s * KC;

    stage_chunk(0, n, h0, cbase);
    cp_commit();                               // pending: {cur.c0}

    while (true) {
        stage_chunk(1, n, h0, cbase + KCS);
        cp_commit();                           // pending: {cur.c0, cur.c1}
        if (tid == 0) s_next = atomicAdd(&g_ctr, 1u);

#pragma unroll
        for (int j = 0; j < 8; j++) { acc0[j] = 0ull; acc1[j] = 0ull; }

        cp_wait<1>();                          // cur.c0 landed
        __syncthreads();
        compute_chunk(0);
        __syncthreads();                       // buf0 free; s_next visible

        unsigned nt = s_next;
        bool have_next = nt < NTILES;
        int nn = 0, nh0 = 0, ncb = 0;
        if (have_next) {
            nn = (nt / 7) & (NN - 1);
            nh0 = (nt % 7) * TH;
            ncb = (nt / 56) * KC;
            stage_chunk(0, nn, nh0, ncb);      // prefetch next tile's chunk0
            cp_commit();                       // pending: {cur.c1, next.c0}
            cp_wait<1>();                      // cur.c1 landed
        } else {
            cp_wait<0>();
        }
        __syncthreads();
        compute_chunk(1);

        // Store partials: g_ypart[s][n][p][c], c contiguous.
        // acc pairs are (c=2j, c=2j+1) packed lo/hi -> memory order matches.
        if (tid < 224) {
            const int p0 = (h0 + r) * WW + wg;
            ulonglong2* yp0 = (ulonglong2*)&g_ypart[((((size_t)s * NN + n) * HWSZ) + p0) * COo];
            ulonglong2* yp1 = (ulonglong2*)&g_ypart[((((size_t)s * NN + n) * HWSZ) + p0 + 28) * COo];
#pragma unroll
            for (int q = 0; q < 4; q++) {
                ulonglong2 v0; v0.x = acc0[2*q]; v0.y = acc0[2*q+1];
                ulonglong2 v1; v1.x = acc1[2*q]; v1.y = acc1[2*q+1];
                yp0[q] = v0;
                yp1[q] = v1;
            }
        }

        if (!have_next) break;
        n = nn; h0 = nh0; cbase = ncb; s = nt / 56;
        __syncthreads();   // everyone done reading buf1 before it's re-staged
    }
}

// ---------------------------------------------------------------------------
// Kernel B: reduce 16 split-K partials, apply fused W = w5@w4 (128x16).
// 448 blocks (one per (row, n)); thread (q=tid/56, px=tid%56): q reduces 4
// slices as float4 vectors (4 x LDG.128 per slice), exchanges via padded
// smem, then emits 32 of the 128 output channels for its pixel.
// ---------------------------------------------------------------------------
__global__ __launch_bounds__(224)
void epilogue_kernel(float* __restrict__ out) {
    __shared__ float Wsh[CC * COo];
    __shared__ __align__(16) float ysh[4][56][20];   // [q][px][c], pad 20
    const int tid = threadIdx.x;
    for (int i = tid; i < CC * COo; i += 224) Wsh[i] = g_W[i];

    const int n  = blockIdx.y;
    const int h  = blockIdx.x;
    const int px = tid % 56;
    const int q  = tid / 56;          // 0..3
    const int p  = h * WW + px;

    // partial reduction: q sums slices 4q..4q+3, all 16 c, as float4s
    float4 y0 = make_float4(0.f,0.f,0.f,0.f), y1 = y0, y2 = y0, y3 = y0;
#pragma unroll
    for (int ss = 0; ss < 4; ss++) {
        int s = q * 4 + ss;
        const float4* src = (const float4*)&g_ypart[(((size_t)s * NN + n) * HWSZ + p) * COo];
        float4 a = src[0], b = src[1], c = src[2], d = src[3];
        y0.x += a.x; y0.y += a.y; y0.z += a.z; y0.w += a.w;
        y1.x += b.x; y1.y += b.y; y1.z += b.z; y1.w += b.w;
        y2.x += c.x; y2.y += c.y; y2.z += c.z; y2.w += c.w;
        y3.x += d.x; y3.y += d.y; y3.z += d.z; y3.w += d.w;
    }
    {
        float4* dst = (float4*)&ysh[q][px][0];
        dst[0] = y0; dst[1] = y1; dst[2] = y2; dst[3] = y3;
    }
    __syncthreads();

    // final y[c] = sum over q' of ysh[q'][px][c]
    float y[COo];
#pragma unroll
    for (int k = 0; k < 4; k++) {
        float4 v0 = *(const float4*)&ysh[0][px][k*4];
        float4 v1 = *(const float4*)&ysh[1][px][k*4];
        float4 v2 = *(const float4*)&ysh[2][px][k*4];
        float4 v3 = *(const float4*)&ysh[3][px][k*4];
        y[k*4+0] = v0.x + v1.x + v2.x + v3.x;
        y[k*4+1] = v0.y + v1.y + v2.y + v3.y;
        y[k*4+2] = v0.z + v1.z + v2.z + v3.z;
        y[k*4+3] = v0.w + v1.w + v2.w + v3.w;
    }

    float* outp = out + ((size_t)n * CC) * HWSZ + p;
#pragma unroll 4
    for (int oo = 0; oo < 32; oo++) {
        int o = q * 32 + oo;
        float v = 0.0f;
#pragma unroll
        for (int j = 0; j < COo; j++) v += Wsh[o * COo + j] * y[j];
        outp[(size_t)o * HWSZ] = v;
    }
}

// ---------------------------------------------------------------------------
extern "C" void kernel_launch(void* const* d_in, const int* in_sizes, int n_in,
                              void* d_out, int out_size) {
    const float* x  = (const float*)d_in[0];
    const float* w3 = (const float*)d_in[1];
    const float* w4 = (const float*)d_in[2];
    const float* w5 = (const float*)d_in[3];
    float* out = (float*)d_out;

    prep_kernel<<<144, 512>>>(w3, w4, w5);
    conv_partial_kernel<<<GRID_A, THREADS_A>>>(x);      // 444 persistent blocks
    dim3 gridB(HH, NN);                                 // 448 blocks
    epilogue_kernel<<<gridB, 224>>>(out);
}

// round 17
// speedup vs baseline: 1.0766x; 1.0176x over previous
#include <cuda_runtime.h>
#include <cstdint>

// Problem constants
#define NN 8
#define CC 128
#define HH 56
#define WW 56
#define COo 16
#define HWSZ (HH*WW)

// Conv tiling (R13-proven configuration)
#define S_SPLIT 16           // K-split over channels (16 groups of 8 channels)
#define KC 8                 // channels per tile
#define KCS 4                // channels per smem chunk (2 chunks per tile)
#define TH 8                 // output rows per tile
#define TROWS 16             // input rows incl. halo
#define TCSTRIDE 92          // 92 % 32 == 28 -> warp-spanning lanes hit disjoint banks
#define THREADS_A 256        // 8 warps: 7 compute warps (8 rows x 28 cols), all 8 stage
#define NTILES 896           // 7 ht x 8 n x 16 s
#define OCC_A 3
#define GRID_A (148*OCC_A)   // 444 persistent blocks = exactly one resident wave
#define WCHUNK (KCS*35*COo)  // 2240 weight floats per chunk = 560 uint4
#define WT_ELEMS (CC*35*COo) // 71680

// Split-K scratch: [s][n][o][p]  (25.7 MB) -- coalesced along p both sides
__device__ __align__(16) float g_ypart[S_SPLIT * NN * COo * HWSZ];
// Transposed conv weights: wT[c][t][o] (o contiguous).
__device__ __align__(16) float g_wT[WT_ELEMS];
// Fused epilogue weights: W = w5 @ w4, [o][j] (128 x 16).
__device__ float g_W[CC * COo];
// Dynamic tile counter (reset by prep each replay; static init covers call #1).
__device__ unsigned g_ctr = GRID_A;

__device__ __forceinline__ unsigned long long pack2(float x) {
    unsigned long long r;
    unsigned int xi = __float_as_uint(x);
    asm("mov.b64 %0, {%1, %1};" : "=l"(r) : "r"(xi));
    return r;
}
__device__ __forceinline__ unsigned long long ffma2(unsigned long long a,
                                                    unsigned long long b,
                                                    unsigned long long c) {
    unsigned long long d;
    asm("fma.rn.f32x2 %0, %1, %2, %3;" : "=l"(d) : "l"(a), "l"(b), "l"(c));
    return d;
}
__device__ __forceinline__ void unpack2(unsigned long long v, float& lo, float& hi) {
    unsigned int l, h;
    asm("mov.b64 {%0, %1}, %2;" : "=r"(l), "=r"(h) : "l"(v));
    lo = __uint_as_float(l);
    hi = __uint_as_float(h);
}

__device__ __forceinline__ void cp_async16(uint32_t dst_smem, const void* src, unsigned src_size) {
    asm volatile("cp.async.cg.shared.global [%0], [%1], 16, %2;\n"
                 :: "r"(dst_smem), "l"(src), "r"(src_size));
}
__device__ __forceinline__ void cp_commit() {
    asm volatile("cp.async.commit_group;\n");
}
template<int N>
__device__ __forceinline__ void cp_wait() {
    asm volatile("cp.async.wait_group %0;\n" :: "n"(N));
}

// ---------------------------------------------------------------------------
// Prep kernel: (a) transpose w3 -> wT[c][t][o]; (b) W = w5 @ w4; (c) reset
// tile counter. Grid 144 x 512: b 0..139 wT, b 140..143 W.
// ---------------------------------------------------------------------------
__global__ __launch_bounds__(512)
void prep_kernel(const float* __restrict__ w3, const float* __restrict__ w4,
                 const float* __restrict__ w5) {
    if (blockIdx.x == 0 && threadIdx.x == 0) g_ctr = GRID_A;
    int b = blockIdx.x;
    if (b < 140) {
        int idx = b * 512 + threadIdx.x;      // 0..71679
        int o  = idx & 15;
        int ct = idx >> 4;                    // c*35 + t
        int c  = ct / 35;
        int t  = ct % 35;
        g_wT[idx] = w3[((size_t)o * CC + c) * 35 + t];
    } else {
        int e = (b - 140) * 512 + threadIdx.x; // 0..2047
        int o = e >> 4, j = e & 15;
        float v = 0.0f;
#pragma unroll
        for (int c = 0; c < COo; c++) v += w5[o * COo + c] * w4[c * COo + j];
        g_W[e] = v;
    }
}

// ---------------------------------------------------------------------------
// Kernel A (R13-proven): dilated 5x7 conv (C->CO), split-K over 16 channel
// groups. Persistent blocks pull tiles dynamically; 16B cp.async
// double-buffered staging. 7 compute warps: 2 pixels (w, w+28) x 16 CO as
// 16 f32x2 regs. Stores partials coalesced as [s][n][o][p].
// ---------------------------------------------------------------------------
__global__ __launch_bounds__(THREADS_A, OCC_A)
void conv_partial_kernel(const float* __restrict__ x) {
    __shared__ __align__(16) float xs[2][KCS][TROWS][TCSTRIDE];
    __shared__ __align__(16) float ws[2][KCS][5][7][COo];   // [buf][ci][kh][kw][o]
    __shared__ unsigned s_next;

    const int tid  = threadIdx.x;
    const int r  = (tid < 224) ? tid / 28 : 0;   // compute row (warps 0..6)
    const int wg = (tid < 224) ? tid % 28 : 0;   // first pixel col (second = +28)

    const uint32_t xs_base = (uint32_t)__cvta_generic_to_shared(&xs[0][0][0][0]);
    const uint32_t ws_base = (uint32_t)__cvta_generic_to_shared(&ws[0][0][0][0]);

    // Stage one KCS-channel chunk of x + weights into buffer `buf` (async).
    auto stage_chunk = [&](int buf, int n, int h0, int cbase_cc) {
#pragma unroll
        for (int i = 0; i < 5; i++) {
            int idx = tid + i * THREADS_A;       // 0..1279
            int row = idx / 20;                  // 0..63
            int v   = idx % 20;                  // 16B vector within row
            int ci  = row >> 4;
            int tr  = row & 15;
            int h_in = h0 - 4 + tr;
            int w0   = v * 4 - 12;               // first w_in of this vector
            bool ok = ((unsigned)h_in < HH) & (w0 >= 0) & (w0 + 3 < WW);
            const float* src = ok
                ? x + (((size_t)n * CC + (cbase_cc + ci)) * HH + h_in) * WW + w0
                : x;                             // valid addr; size=0 -> zfill
            uint32_t dst = xs_base +
                (((buf * KCS + ci) * TROWS + tr) * TCSTRIDE + v * 4) * 4;
            cp_async16(dst, src, ok ? 16u : 0u);
        }
        const float* wsrc = g_wT + (size_t)cbase_cc * 35 * COo;
        uint32_t wdst = ws_base + (buf * WCHUNK) * 4;
#pragma unroll
        for (int i = 0; i < 3; i++) {
            int k = tid + i * THREADS_A;
            if (k < WCHUNK / 4)
                cp_async16(wdst + k * 16, wsrc + k * 4, 16u);
        }
    };

    unsigned long long acc0[8], acc1[8];
    auto compute_chunk = [&](int buf) {
        if (tid >= 224) return;
#pragma unroll
        for (int ci = 0; ci < KCS; ci++) {
#pragma unroll
            for (int kh = 0; kh < 5; kh++) {
                const float* xrow = &xs[buf][ci][r + 2 * kh][0];
#pragma unroll
                for (int kw = 0; kw < 7; kw++) {
                    // staged col = w_in + 12; needed w_in = px - 9 + 3kw
                    float xa = xrow[wg + 3 * kw + 3];
                    float xb = xrow[wg + 28 + 3 * kw + 3];
                    unsigned long long xa2 = pack2(xa);
                    unsigned long long xb2 = pack2(xb);
                    const ulonglong2* wp = (const ulonglong2*)&ws[buf][ci][kh][kw][0];
#pragma unroll
                    for (int q = 0; q < 4; q++) {
                        ulonglong2 wv = wp[q];
                        acc0[2*q]   = ffma2(xa2, wv.x, acc0[2*q]);
                        acc0[2*q+1] = ffma2(xa2, wv.y, acc0[2*q+1]);
                        acc1[2*q]   = ffma2(xb2, wv.x, acc1[2*q]);
                        acc1[2*q+1] = ffma2(xb2, wv.y, acc1[2*q+1]);
                    }
                }
            }
        }
    };

    unsigned tile = blockIdx.x;
    int n  = (tile / 7) & (NN - 1);
    int s  = tile / 56;
    int h0 = (tile % 7) * TH;
    int cbase = s * KC;

    stage_chunk(0, n, h0, cbase);
    cp_commit();                               // pending: {cur.c0}

    while (true) {
        stage_chunk(1, n, h0, cbase + KCS);
        cp_commit();                           // pending: {cur.c0, cur.c1}
        if (tid == 0) s_next = atomicAdd(&g_ctr, 1u);

#pragma unroll
        for (int j = 0; j < 8; j++) { acc0[j] = 0ull; acc1[j] = 0ull; }

        cp_wait<1>();                          // cur.c0 landed
        __syncthreads();
        compute_chunk(0);
        __syncthreads();                       // buf0 free; s_next visible

        unsigned nt = s_next;
        bool have_next = nt < NTILES;
        int nn = 0, nh0 = 0, ncb = 0;
        if (have_next) {
            nn = (nt / 7) & (NN - 1);
            nh0 = (nt % 7) * TH;
            ncb = (nt / 56) * KC;
            stage_chunk(0, nn, nh0, ncb);      // prefetch next tile's chunk0
            cp_commit();                       // pending: {cur.c1, next.c0}
            cp_wait<1>();                      // cur.c1 landed
        } else {
            cp_wait<0>();
        }
        __syncthreads();
        compute_chunk(1);

        // Store partials coalesced: g_ypart[s][n][o][h*56 + w]
        if (tid < 224) {
            const int h = h0 + r;
            float* yp = &g_ypart[(((size_t)s * NN + n) * COo) * HWSZ + h * WW];
#pragma unroll
            for (int j = 0; j < 8; j++) {
                float lo, hi;
                unpack2(acc0[j], lo, hi);
                yp[(2*j)   * HWSZ + wg] = lo;
                yp[(2*j+1) * HWSZ + wg] = hi;
                unpack2(acc1[j], lo, hi);
                yp[(2*j)   * HWSZ + wg + 28] = lo;
                yp[(2*j+1) * HWSZ + wg + 28] = hi;
            }
        }

        if (!have_next) break;
        n = nn; h0 = nh0; cbase = ncb; s = nt / 56;
        __syncthreads();   // everyone done reading buf1 before it's re-staged
    }
}

// ---------------------------------------------------------------------------
// Kernel B: reduce 16 split-K partials, apply fused W = w5@w4 (128x16).
// 448 blocks (one per (row, n)), 224 threads = (c 0..15, pg 0..13).
// Phase 1: thread (c,pg) reduces its float4 pixel group over all 16 slices
//          (16 x LDG.128, contiguous 224B across pg lanes).
// Phase 2: thread (u=c,pg) computes 8 output channels o = u+16t for its 4
//          pixels with FFMA2 against Wsh[j][o]; 8 x STG.128, coalesced.
// ---------------------------------------------------------------------------
__global__ __launch_bounds__(224)
void epilogue_kernel(float* __restrict__ out) {
    __shared__ float Wsh[COo * CC];                 // [j][o] transposed
    __shared__ __align__(16) float4 ysh[COo][14];   // [c][pg]
    const int tid = threadIdx.x;

    // Load W transposed: Wsh[j][o] = g_W[o][j] (coalesced LDG, scattered STS once)
    for (int i = tid; i < CC * COo; i += 224) {
        int o = i >> 4, j = i & 15;
        Wsh[j * CC + o] = g_W[i];
    }

    const int n  = blockIdx.y;
    const int h  = blockIdx.x;
    const int c  = tid / 14;          // channel 0..15 (phase 1) / u (phase 2)
    const int pg = tid % 14;          // float4 pixel group within the row
    const int p4 = h * WW + pg * 4;

    // Phase 1: reduce over the 16 s-slices, vectorized along pixels
    float4 acc = make_float4(0.f, 0.f, 0.f, 0.f);
#pragma unroll
    for (int s = 0; s < S_SPLIT; s++) {
        float4 v = *(const float4*)&g_ypart[(((size_t)s * NN + n) * COo + c) * HWSZ + p4];
        acc.x += v.x; acc.y += v.y; acc.z += v.z; acc.w += v.w;
    }
    ysh[c][pg] = acc;
    __syncthreads();

    // Phase 2: o = c + 16t for t = 0..7, 4 pixels each, via FFMA2
    unsigned long long vacc[8][2];
#pragma unroll
    for (int t = 0; t < 8; t++) { vacc[t][0] = 0ull; vacc[t][1] = 0ull; }

#pragma unroll
    for (int j = 0; j < COo; j++) {
        ulonglong2 yv = *(const ulonglong2*)&ysh[j][pg];
        const float* wrow = &Wsh[j * CC + c];   // + 16t per t; broadcast across pg
#pragma unroll
        for (int t = 0; t < 8; t++) {
            unsigned long long w2 = pack2(wrow[16 * t]);
            vacc[t][0] = ffma2(w2, yv.x, vacc[t][0]);
            vacc[t][1] = ffma2(w2, yv.y, vacc[t][1]);
        }
    }

    float* outp = out + ((size_t)n * CC) * HWSZ + p4;
#pragma unroll
    for (int t = 0; t < 8; t++) {
        int o = c + 16 * t;
        float4 v;
        unpack2(vacc[t][0], v.x, v.y);
        unpack2(vacc[t][1], v.z, v.w);
        *(float4*)(outp + (size_t)o * HWSZ) = v;
    }
}

// ---------------------------------------------------------------------------
extern "C" void kernel_launch(void* const* d_in, const int* in_sizes, int n_in,
                              void* d_out, int out_size) {
    const float* x  = (const float*)d_in[0];
    const float* w3 = (const float*)d_in[1];
    const float* w4 = (const float*)d_in[2];
    const float* w5 = (const float*)d_in[3];
    float* out = (float*)d_out;

    prep_kernel<<<144, 512>>>(w3, w4, w5);
    conv_partial_kernel<<<GRID_A, THREADS_A>>>(x);      // 444 persistent blocks
    dim3 gridB(HH, NN);                                 // 448 blocks
    epilogue_kernel<<<gridB, 224>>>(out);
}